// round 10
// baseline (speedup 1.0000x reference)
#include <cuda_runtime.h>

#define NN 50000
#define NE 600000
#define NR 500
#define NF 128
#define NH 4
#define EPB (NE / NN)   // 12 edges per k_pre block

typedef unsigned long long ull;

// ---------------- device scratch (zero-initialized at module load) ----------------
__device__ float4 g_nl[NN];         // node logits (4 heads)
__device__ float4 g_rl[NR];         // relation logits (4 heads)
__device__ int    g_deg[NN];        // zeroed by k_scanA for next run
__device__ int    g_rowptr[NN];     // bucket start
__device__ int    g_end[NN];        // bucket end
__device__ int    g_cursor[NN];
__device__ int2   g_esr[NE];        // per-slot (src, rel)
__device__ float4 g_ew[NE];         // per-slot 4-head edge weights e_h
__device__ int    g_total;          // reset by k_agg for next run

// ---------------- helpers ----------------
__device__ __forceinline__ ull pk2(float lo, float hi) {
    ull r; asm("mov.b64 %0, {%1, %2};" : "=l"(r) : "f"(lo), "f"(hi)); return r;
}
__device__ __forceinline__ float2 upk2(ull v) {
    float2 r; asm("mov.b64 {%0, %1}, %2;" : "=f"(r.x), "=f"(r.y) : "l"(v)); return r;
}
__device__ __forceinline__ ull ff2(ull a, ull b, ull c) {
    ull r; asm("fma.rn.f32x2 %0, %1, %2, %3;" : "=l"(r) : "l"(a), "l"(b), "l"(c)); return r;
}
__device__ __forceinline__ float edge_e(float x) {
    float l = x > 0.f ? x : 0.2f * x;
    return __expf(-l);
}
// per-warp int64-vs-int32 detect (dst = arange(N): int64 => odd words 0)
__device__ __forceinline__ int detect64(const int* A32) {
    int v = A32[2 * (threadIdx.x & 31) + 1];
    return __ballot_sync(0xffffffffu, v != 0) == 0u;
}

// block-of-128 reduction
__device__ __forceinline__ void reduce4_store(float v0, float v1, float v2, float v3,
                                              float* dst4) {
    int f = threadIdx.x;
#pragma unroll
    for (int off = 16; off > 0; off >>= 1) {
        v0 += __shfl_down_sync(0xffffffffu, v0, off);
        v1 += __shfl_down_sync(0xffffffffu, v1, off);
        v2 += __shfl_down_sync(0xffffffffu, v2, off);
        v3 += __shfl_down_sync(0xffffffffu, v3, off);
    }
    __shared__ float sp[4][4];
    if ((f & 31) == 0) {
        int wg = f >> 5;
        sp[wg][0] = v0; sp[wg][1] = v1; sp[wg][2] = v2; sp[wg][3] = v3;
    }
    __syncthreads();
    if (f < 4) dst4[f] = sp[0][f] + sp[1][f] + sp[2][f] + sp[3][f];
    __syncthreads();
}

// ---------------- 0: fused logits + degree histogram ----------------
__global__ void k_pre(const float* __restrict__ h0, const float* __restrict__ inputr,
                      const float* __restrict__ w, const float* __restrict__ a,
                      const void* __restrict__ A) {
    int n = blockIdx.x, f = threadIdx.x;
    __shared__ int s_is64;
    if (f < 32) {
        int is64 = detect64((const int*)A);
        if (f == 0) s_is64 = is64;
    }

    float hv = h0[n * NF + f];
    float cw = 1.f;
    float v0 = hv * a[0 * 2 * NF + f];
    cw *= w[0 * NF + f];
    float v1 = hv * cw * a[1 * 2 * NF + f];
    cw *= w[1 * NF + f];
    float v2 = hv * cw * a[2 * 2 * NF + f];
    cw *= w[2 * NF + f];
    float v3 = hv * cw * a[3 * 2 * NF + f];
    reduce4_store(v0, v1, v2, v3, (float*)&g_nl[n]);

    if (n < NR) {
        float rv = inputr[n * NF + f];
        reduce4_store(rv * a[0 * 2 * NF + NF + f], rv * a[1 * 2 * NF + NF + f],
                      rv * a[2 * 2 * NF + NF + f], rv * a[3 * 2 * NF + NF + f],
                      (float*)&g_rl[n]);
    }

    if (f < EPB) {
        int e = n * EPB + f;
        int dst = s_is64 ? (int)((const long long*)A)[e] : ((const int*)A)[e];
        atomicAdd(&g_deg[dst], 1);
    }
}

// ---------------- 1: scan via atomic block base; self-cleans g_deg ----------------
__global__ void k_scanA() {
    __shared__ int s[256];
    __shared__ int base;
    int tid = threadIdx.x;
    int i = blockIdx.x * 256 + tid;
    int v = (i < NN) ? g_deg[i] : 0;
    s[tid] = v;
    __syncthreads();
#pragma unroll
    for (int off = 1; off < 256; off <<= 1) {
        int t = (tid >= off) ? s[tid - off] : 0;
        __syncthreads();
        s[tid] += t;
        __syncthreads();
    }
    if (tid == 255) base = atomicAdd(&g_total, s[255]);
    __syncthreads();
    if (i < NN) {
        int r = base + s[tid] - v;
        g_rowptr[i] = r;
        g_end[i]    = r + v;
        g_cursor[i] = r;
        g_deg[i]    = 0;      // clean for next launch
    }
}

// ---------------- 2: scatter + edge-weight precompute ----------------
__global__ void k_scatter(const void* __restrict__ A) {
    int is64 = detect64((const int*)A);
    int e = blockIdx.x * blockDim.x + threadIdx.x;
    if (e >= NE) return;
    int dst, rel, src;
    if (is64) {
        const long long* a = (const long long*)A;
        dst = (int)a[e]; rel = (int)a[NE + e]; src = (int)a[2 * NE + e];
    } else {
        const int* a = (const int*)A;
        dst = a[e]; rel = a[NE + e]; src = a[2 * NE + e];
    }
    float4 nl = g_nl[src];
    float4 rl = g_rl[rel];
    float4 ev;
    ev.x = edge_e(nl.x + rl.x);
    ev.y = edge_e(nl.y + rl.y);
    ev.z = edge_e(nl.z + rl.z);
    ev.w = edge_e(nl.w + rl.w);
    int pos = atomicAdd(&g_cursor[dst], 1);
    g_esr[pos] = make_int2(src, rel);
    g_ew[pos]  = ev;
}

// ---------------- 3: aggregation, one warp per dst node (proven inner loop) ----------------
__global__ void __launch_bounds__(32) k_agg(const float4* __restrict__ h4,
                                            const float4* __restrict__ r4,
                                            const float* __restrict__ w,
                                            float* __restrict__ out) {
    int n = blockIdx.x;
    int t = threadIdx.x;
    if (n == 0 && t == 0) g_total = 0;    // clean for next launch
    int beg = g_rowptr[n];
    int end = g_end[n];

    ull aH0 = 0, aH1 = 0, aH2 = 0, aH3 = 0, aH4 = 0, aH5 = 0, aH6 = 0, aH7 = 0;
    ull aR0 = 0, aR1 = 0, aR2 = 0, aR3 = 0, aR4 = 0, aR5 = 0, aR6 = 0, aR7 = 0;
    float rs0 = 0.f, rs1 = 0.f, rs2 = 0.f, rs3 = 0.f;

    __shared__ float4 s_e[32];
    __shared__ int s_src[32];
    __shared__ int s_rel[32];

    for (int base = beg; base < end; base += 32) {
        int c = end - base;
        if (c > 32) c = 32;
        if (t < c) {
            int2 sr = g_esr[base + t];     // contiguous 8B
            s_src[t] = sr.x;
            s_rel[t] = sr.y;
            s_e[t]   = g_ew[base + t];     // contiguous 16B, weights precomputed
        }
        __syncwarp();
#pragma unroll 2
        for (int j = 0; j < c; j++) {
            int src = s_src[j], rel = s_rel[j];
            float4 hv = h4[src * 32 + t];
            float4 rv = r4[rel * 32 + t];
            float4 ev = s_e[j];
            ull hA = pk2(hv.x, hv.y), hB = pk2(hv.z, hv.w);
            ull rA = pk2(rv.x, rv.y), rB = pk2(rv.z, rv.w);
            ull e;
            e = pk2(ev.x, ev.x);
            aH0 = ff2(hA, e, aH0); aH1 = ff2(hB, e, aH1);
            aR0 = ff2(rA, e, aR0); aR1 = ff2(rB, e, aR1);
            e = pk2(ev.y, ev.y);
            aH2 = ff2(hA, e, aH2); aH3 = ff2(hB, e, aH3);
            aR2 = ff2(rA, e, aR2); aR3 = ff2(rB, e, aR3);
            e = pk2(ev.z, ev.z);
            aH4 = ff2(hA, e, aH4); aH5 = ff2(hB, e, aH5);
            aR4 = ff2(rA, e, aR4); aR5 = ff2(rB, e, aR5);
            e = pk2(ev.w, ev.w);
            aH6 = ff2(hA, e, aH6); aH7 = ff2(hB, e, aH7);
            aR6 = ff2(rA, e, aR6); aR7 = ff2(rB, e, aR7);
            rs0 += ev.x; rs1 += ev.y; rs2 += ev.z; rs3 += ev.w;
        }
        __syncwarp();
    }

    float4 w0 = *(const float4*)&w[0 * NF + 4 * t];
    float4 w1 = *(const float4*)&w[1 * NF + 4 * t];
    float4 w2 = *(const float4*)&w[2 * NF + 4 * t];
    float4 cw1 = w0;
    float4 cw2 = make_float4(cw1.x * w1.x, cw1.y * w1.y, cw1.z * w1.z, cw1.w * w1.w);
    float4 cw3 = make_float4(cw2.x * w2.x, cw2.y * w2.y, cw2.z * w2.z, cw2.w * w2.w);

    float i0 = 1.f / rs0, i1 = 1.f / rs1, i2 = 1.f / rs2, i3 = 1.f / rs3;
    float4* o4 = (float4*)out;
    float2 hp, rp;
    float4 o;

    hp = upk2(aH0); rp = upk2(aR0);
    o.x = (hp.x - rp.x) * i0; o.y = (hp.y - rp.y) * i0;
    hp = upk2(aH1); rp = upk2(aR1);
    o.z = (hp.x - rp.x) * i0; o.w = (hp.y - rp.y) * i0;
    o4[(0 * NN + n) * 32 + t] = o;

    hp = upk2(aH2); rp = upk2(aR2);
    o.x = (cw1.x * hp.x - rp.x) * i1; o.y = (cw1.y * hp.y - rp.y) * i1;
    hp = upk2(aH3); rp = upk2(aR3);
    o.z = (cw1.z * hp.x - rp.x) * i1; o.w = (cw1.w * hp.y - rp.y) * i1;
    o4[(1 * NN + n) * 32 + t] = o;

    hp = upk2(aH4); rp = upk2(aR4);
    o.x = (cw2.x * hp.x - rp.x) * i2; o.y = (cw2.y * hp.y - rp.y) * i2;
    hp = upk2(aH5); rp = upk2(aR5);
    o.z = (cw2.z * hp.x - rp.x) * i2; o.w = (cw2.w * hp.y - rp.y) * i2;
    o4[(2 * NN + n) * 32 + t] = o;

    hp = upk2(aH6); rp = upk2(aR6);
    o.x = (cw3.x * hp.x - rp.x) * i3; o.y = (cw3.y * hp.y - rp.y) * i3;
    hp = upk2(aH7); rp = upk2(aR7);
    o.z = (cw3.z * hp.x - rp.x) * i3; o.w = (cw3.w * hp.y - rp.y) * i3;
    o4[(3 * NN + n) * 32 + t] = o;
}

// ---------------- launch ----------------
extern "C" void kernel_launch(void* const* d_in, const int* in_sizes, int n_in,
                              void* d_out, int out_size) {
    const float* h0     = (const float*)d_in[0];
    const float* inputr = (const float*)d_in[1];
    const float* w      = (const float*)d_in[2];
    const float* a      = (const float*)d_in[3];
    const void*  A      = d_in[4];
    float* out = (float*)d_out;

    int nbN = (NN + 255) / 256;
    int nbE = (NE + 255) / 256;

    k_pre<<<NN, NF>>>(h0, inputr, w, a, A);            // my launch 0
    k_scanA<<<nbN, 256>>>();                           // my launch 1
    k_scatter<<<nbE, 256>>>(A);                        // my launch 2
    k_agg<<<NN, 32>>>((const float4*)h0, (const float4*)inputr, w, out);  // my launch 3
}

// round 11
// speedup vs baseline: 1.0827x; 1.0827x over previous
#include <cuda_runtime.h>

#define NN 50000
#define NE 600000
#define NR 500
#define NF 128
#define NH 4
#define EPB (NE / NN)   // 12 edges per k_pre block

typedef unsigned long long ull;

// ---------------- device scratch (zero-initialized at module load) ----------------
__device__ float4 g_nl[NN];         // node logits (4 heads)
__device__ float4 g_rl[NR];         // relation logits (4 heads)
__device__ int    g_deg[NN];        // zeroed by k_scanA for next run
__device__ int    g_rowptr[NN];     // bucket start
__device__ int    g_end[NN];        // bucket end
__device__ int    g_cursor[NN];
__device__ int2   g_edges[NE];      // (src, rel) grouped by dst
__device__ int    g_total;          // reset by k_agg for next run

// ---------------- helpers ----------------
__device__ __forceinline__ ull pk2(float lo, float hi) {
    ull r; asm("mov.b64 %0, {%1, %2};" : "=l"(r) : "f"(lo), "f"(hi)); return r;
}
__device__ __forceinline__ float2 upk2(ull v) {
    float2 r; asm("mov.b64 {%0, %1}, %2;" : "=f"(r.x), "=f"(r.y) : "l"(v)); return r;
}
__device__ __forceinline__ ull ff2(ull a, ull b, ull c) {
    ull r; asm("fma.rn.f32x2 %0, %1, %2, %3;" : "=l"(r) : "l"(a), "l"(b), "l"(c)); return r;
}
__device__ __forceinline__ float edge_e(float x) {
    float l = x > 0.f ? x : 0.2f * x;
    return __expf(-l);
}
// per-warp int64-vs-int32 detect (dst = arange(N): int64 => odd words 0)
__device__ __forceinline__ int detect64(const int* A32) {
    int v = A32[2 * (threadIdx.x & 31) + 1];
    return __ballot_sync(0xffffffffu, v != 0) == 0u;
}

// block-of-128 reduction
__device__ __forceinline__ void reduce4_store(float v0, float v1, float v2, float v3,
                                              float* dst4) {
    int f = threadIdx.x;
#pragma unroll
    for (int off = 16; off > 0; off >>= 1) {
        v0 += __shfl_down_sync(0xffffffffu, v0, off);
        v1 += __shfl_down_sync(0xffffffffu, v1, off);
        v2 += __shfl_down_sync(0xffffffffu, v2, off);
        v3 += __shfl_down_sync(0xffffffffu, v3, off);
    }
    __shared__ float sp[4][4];
    if ((f & 31) == 0) {
        int wg = f >> 5;
        sp[wg][0] = v0; sp[wg][1] = v1; sp[wg][2] = v2; sp[wg][3] = v3;
    }
    __syncthreads();
    if (f < 4) dst4[f] = sp[0][f] + sp[1][f] + sp[2][f] + sp[3][f];
    __syncthreads();
}

// ---------------- 0: fused logits + degree histogram ----------------
__global__ void k_pre(const float* __restrict__ h0, const float* __restrict__ inputr,
                      const float* __restrict__ w, const float* __restrict__ a,
                      const void* __restrict__ A) {
    int n = blockIdx.x, f = threadIdx.x;
    __shared__ int s_is64;
    if (f < 32) {
        int is64 = detect64((const int*)A);
        if (f == 0) s_is64 = is64;
    }

    float hv = h0[n * NF + f];
    float cw = 1.f;
    float v0 = hv * a[0 * 2 * NF + f];
    cw *= w[0 * NF + f];
    float v1 = hv * cw * a[1 * 2 * NF + f];
    cw *= w[1 * NF + f];
    float v2 = hv * cw * a[2 * 2 * NF + f];
    cw *= w[2 * NF + f];
    float v3 = hv * cw * a[3 * 2 * NF + f];
    reduce4_store(v0, v1, v2, v3, (float*)&g_nl[n]);

    if (n < NR) {
        float rv = inputr[n * NF + f];
        reduce4_store(rv * a[0 * 2 * NF + NF + f], rv * a[1 * 2 * NF + NF + f],
                      rv * a[2 * 2 * NF + NF + f], rv * a[3 * 2 * NF + NF + f],
                      (float*)&g_rl[n]);
    }

    if (f < EPB) {
        int e = n * EPB + f;
        int dst = s_is64 ? (int)((const long long*)A)[e] : ((const int*)A)[e];
        atomicAdd(&g_deg[dst], 1);
    }
}

// ---------------- 1: scan via atomic block base; self-cleans g_deg ----------------
__global__ void k_scanA() {
    __shared__ int s[256];
    __shared__ int base;
    int tid = threadIdx.x;
    int i = blockIdx.x * 256 + tid;
    int v = (i < NN) ? g_deg[i] : 0;
    s[tid] = v;
    __syncthreads();
#pragma unroll
    for (int off = 1; off < 256; off <<= 1) {
        int t = (tid >= off) ? s[tid - off] : 0;
        __syncthreads();
        s[tid] += t;
        __syncthreads();
    }
    if (tid == 255) base = atomicAdd(&g_total, s[255]);
    __syncthreads();
    if (i < NN) {
        int r = base + s[tid] - v;
        g_rowptr[i] = r;
        g_end[i]    = r + v;
        g_cursor[i] = r;
        g_deg[i]    = 0;      // clean for next launch
    }
}

// ---------------- 2: scatter edges into CSR buckets (2 edges/thread) ----------------
__global__ void k_scatter(const void* __restrict__ A) {
    int is64 = detect64((const int*)A);
    int p = blockIdx.x * blockDim.x + threadIdx.x;
    if (p >= NE / 2) return;
    int d0, d1, r0, r1, s0, s1;
    if (is64) {
        const longlong2* a = (const longlong2*)A;
        longlong2 vd = a[p];
        longlong2 vr = a[NE / 2 + p];
        longlong2 vs = a[NE + p];
        d0 = (int)vd.x; d1 = (int)vd.y;
        r0 = (int)vr.x; r1 = (int)vr.y;
        s0 = (int)vs.x; s1 = (int)vs.y;
    } else {
        const int2* a = (const int2*)A;
        int2 vd = a[p];
        int2 vr = a[NE / 2 + p];
        int2 vs = a[NE + p];
        d0 = vd.x; d1 = vd.y;
        r0 = vr.x; r1 = vr.y;
        s0 = vs.x; s1 = vs.y;
    }
    int p0 = atomicAdd(&g_cursor[d0], 1);
    g_edges[p0] = make_int2(s0, r0);
    int p1 = atomicAdd(&g_cursor[d1], 1);
    g_edges[p1] = make_int2(s1, r1);
}

// ---------------- 3: aggregation, one warp per dst node ----------------
__global__ void __launch_bounds__(32) k_agg(const float4* __restrict__ h4,
                                            const float4* __restrict__ r4,
                                            const float* __restrict__ w,
                                            float* __restrict__ out) {
    int n = blockIdx.x;
    int t = threadIdx.x;
    if (n == 0 && t == 0) g_total = 0;    // clean for next launch
    int beg = g_rowptr[n];
    int end = g_end[n];

    ull aH0 = 0, aH1 = 0, aH2 = 0, aH3 = 0, aH4 = 0, aH5 = 0, aH6 = 0, aH7 = 0;
    ull aR0 = 0, aR1 = 0, aR2 = 0, aR3 = 0, aR4 = 0, aR5 = 0, aR6 = 0, aR7 = 0;
    // per-lane rowsum partials: lane t owns edges it staged
    float prs0 = 0.f, prs1 = 0.f, prs2 = 0.f, prs3 = 0.f;

    __shared__ float4 s_e[32];
    __shared__ int2 s_sr[32];

    for (int base = beg; base < end; base += 32) {
        int c = end - base;
        if (c > 32) c = 32;
        if (t < c) {
            int2 er = g_edges[base + t];
            float4 nl = g_nl[er.x];
            float4 rl = g_rl[er.y];
            float4 ev;
            ev.x = edge_e(nl.x + rl.x);
            ev.y = edge_e(nl.y + rl.y);
            ev.z = edge_e(nl.z + rl.z);
            ev.w = edge_e(nl.w + rl.w);
            s_e[t]  = ev;
            s_sr[t] = er;
            prs0 += ev.x; prs1 += ev.y; prs2 += ev.z; prs3 += ev.w;
        }
        __syncwarp();
#pragma unroll 4
        for (int j = 0; j < c; j++) {
            int2 sr = s_sr[j];
            float4 hv = h4[sr.x * 32 + t];
            float4 rv = r4[sr.y * 32 + t];
            float4 ev = s_e[j];
            ull hA = pk2(hv.x, hv.y), hB = pk2(hv.z, hv.w);
            ull rA = pk2(rv.x, rv.y), rB = pk2(rv.z, rv.w);
            ull e;
            e = pk2(ev.x, ev.x);
            aH0 = ff2(hA, e, aH0); aH1 = ff2(hB, e, aH1);
            aR0 = ff2(rA, e, aR0); aR1 = ff2(rB, e, aR1);
            e = pk2(ev.y, ev.y);
            aH2 = ff2(hA, e, aH2); aH3 = ff2(hB, e, aH3);
            aR2 = ff2(rA, e, aR2); aR3 = ff2(rB, e, aR3);
            e = pk2(ev.z, ev.z);
            aH4 = ff2(hA, e, aH4); aH5 = ff2(hB, e, aH5);
            aR4 = ff2(rA, e, aR4); aR5 = ff2(rB, e, aR5);
            e = pk2(ev.w, ev.w);
            aH6 = ff2(hA, e, aH6); aH7 = ff2(hB, e, aH7);
            aR6 = ff2(rA, e, aR6); aR7 = ff2(rB, e, aR7);
        }
        __syncwarp();
    }

    // rowsum all-reduce across lanes (each lane holds partial from edges it staged)
#pragma unroll
    for (int off = 16; off > 0; off >>= 1) {
        prs0 += __shfl_xor_sync(0xffffffffu, prs0, off);
        prs1 += __shfl_xor_sync(0xffffffffu, prs1, off);
        prs2 += __shfl_xor_sync(0xffffffffu, prs2, off);
        prs3 += __shfl_xor_sync(0xffffffffu, prs3, off);
    }

    float4 w0 = *(const float4*)&w[0 * NF + 4 * t];
    float4 w1 = *(const float4*)&w[1 * NF + 4 * t];
    float4 w2 = *(const float4*)&w[2 * NF + 4 * t];
    float4 cw1 = w0;
    float4 cw2 = make_float4(cw1.x * w1.x, cw1.y * w1.y, cw1.z * w1.z, cw1.w * w1.w);
    float4 cw3 = make_float4(cw2.x * w2.x, cw2.y * w2.y, cw2.z * w2.z, cw2.w * w2.w);

    float i0 = 1.f / prs0, i1 = 1.f / prs1, i2 = 1.f / prs2, i3 = 1.f / prs3;
    float4* o4 = (float4*)out;
    float2 hp, rp;
    float4 o;

    hp = upk2(aH0); rp = upk2(aR0);
    o.x = (hp.x - rp.x) * i0; o.y = (hp.y - rp.y) * i0;
    hp = upk2(aH1); rp = upk2(aR1);
    o.z = (hp.x - rp.x) * i0; o.w = (hp.y - rp.y) * i0;
    o4[(0 * NN + n) * 32 + t] = o;

    hp = upk2(aH2); rp = upk2(aR2);
    o.x = (cw1.x * hp.x - rp.x) * i1; o.y = (cw1.y * hp.y - rp.y) * i1;
    hp = upk2(aH3); rp = upk2(aR3);
    o.z = (cw1.z * hp.x - rp.x) * i1; o.w = (cw1.w * hp.y - rp.y) * i1;
    o4[(1 * NN + n) * 32 + t] = o;

    hp = upk2(aH4); rp = upk2(aR4);
    o.x = (cw2.x * hp.x - rp.x) * i2; o.y = (cw2.y * hp.y - rp.y) * i2;
    hp = upk2(aH5); rp = upk2(aR5);
    o.z = (cw2.z * hp.x - rp.x) * i2; o.w = (cw2.w * hp.y - rp.y) * i2;
    o4[(2 * NN + n) * 32 + t] = o;

    hp = upk2(aH6); rp = upk2(aR6);
    o.x = (cw3.x * hp.x - rp.x) * i3; o.y = (cw3.y * hp.y - rp.y) * i3;
    hp = upk2(aH7); rp = upk2(aR7);
    o.z = (cw3.z * hp.x - rp.x) * i3; o.w = (cw3.w * hp.y - rp.y) * i3;
    o4[(3 * NN + n) * 32 + t] = o;
}

// ---------------- launch ----------------
extern "C" void kernel_launch(void* const* d_in, const int* in_sizes, int n_in,
                              void* d_out, int out_size) {
    const float* h0     = (const float*)d_in[0];
    const float* inputr = (const float*)d_in[1];
    const float* w      = (const float*)d_in[2];
    const float* a      = (const float*)d_in[3];
    const void*  A      = d_in[4];
    float* out = (float*)d_out;

    int nbN  = (NN + 255) / 256;
    int nbE2 = (NE / 2 + 255) / 256;

    k_pre<<<NN, NF>>>(h0, inputr, w, a, A);            // my launch 0
    k_scanA<<<nbN, 256>>>();                           // my launch 1
    k_scatter<<<nbE2, 256>>>(A);                       // my launch 2
    k_agg<<<NN, 32>>>((const float4*)h0, (const float4*)inputr, w, out);  // my launch 3
}

// round 12
// speedup vs baseline: 1.3314x; 1.2297x over previous
#include <cuda_runtime.h>

#define NN 50000
#define NE 600000
#define NR 500
#define NF 128
#define NH 4

typedef unsigned long long ull;

// ---------------- device scratch (zero-initialized at module load) ----------------
__device__ float4 g_nl[NN];         // node logits (4 heads)
__device__ float4 g_rl[NR];         // relation logits (4 heads)
__device__ int    g_deg[NN];        // zeroed by k_scanA for next run
__device__ int    g_rowptr[NN];     // bucket start
__device__ int    g_end[NN];        // bucket end
__device__ int    g_cursor[NN];
__device__ int2   g_edges[NE];      // (src, rel) grouped by dst
__device__ int    g_total;          // reset by k_agg for next run

// ---------------- helpers ----------------
__device__ __forceinline__ ull pk2(float lo, float hi) {
    ull r; asm("mov.b64 %0, {%1, %2};" : "=l"(r) : "f"(lo), "f"(hi)); return r;
}
__device__ __forceinline__ float2 upk2(ull v) {
    float2 r; asm("mov.b64 {%0, %1}, %2;" : "=f"(r.x), "=f"(r.y) : "l"(v)); return r;
}
__device__ __forceinline__ ull ff2(ull a, ull b, ull c) {
    ull r; asm("fma.rn.f32x2 %0, %1, %2, %3;" : "=l"(r) : "l"(a), "l"(b), "l"(c)); return r;
}
__device__ __forceinline__ float edge_e(float x) {
    float l = x > 0.f ? x : 0.2f * x;
    return __expf(-l);
}
__device__ __forceinline__ float dot4(float4 x, float4 y) {
    return x.x * y.x + x.y * y.y + x.z * y.z + x.w * y.w;
}
// per-warp int64-vs-int32 detect (dst = arange(N): int64 => odd words 0)
__device__ __forceinline__ int detect64(const int* A32) {
    int v = A32[2 * (threadIdx.x & 31) + 1];
    return __ballot_sync(0xffffffffu, v != 0) == 0u;
}

// ---------------- 0: warp-per-node logits + degree histogram ----------------
// block = 256 threads = 8 warps = 8 nodes; block also histograms its 96 edges.
__global__ void __launch_bounds__(256) k_pre(const float4* __restrict__ h4,
                                             const float4* __restrict__ r4,
                                             const float* __restrict__ w,
                                             const float* __restrict__ a,
                                             const void* __restrict__ A) {
    int tid  = threadIdx.x;
    int wrp  = tid >> 5;
    int lane = tid & 31;
    int n = blockIdx.x * 8 + wrp;

    __shared__ int s_is64;
    if (wrp == 0) {
        int is64 = detect64((const int*)A);
        if (lane == 0) s_is64 = is64;
    }

    // ---- node logits (warp-local, shuffle reduce) ----
    {
        const float4* af = (const float4*)a;
        float4 hv = h4[n * 32 + lane];
        float4 w0 = *(const float4*)&w[0 * NF + 4 * lane];
        float4 w1 = *(const float4*)&w[1 * NF + 4 * lane];
        float4 w2 = *(const float4*)&w[2 * NF + 4 * lane];
        float4 av;
        float4 cwh = hv;
        av = af[(0 * 2 * NF) / 4 + lane];
        float v0 = dot4(cwh, av);
        cwh.x *= w0.x; cwh.y *= w0.y; cwh.z *= w0.z; cwh.w *= w0.w;
        av = af[(1 * 2 * NF) / 4 + lane];
        float v1 = dot4(cwh, av);
        cwh.x *= w1.x; cwh.y *= w1.y; cwh.z *= w1.z; cwh.w *= w1.w;
        av = af[(2 * 2 * NF) / 4 + lane];
        float v2 = dot4(cwh, av);
        cwh.x *= w2.x; cwh.y *= w2.y; cwh.z *= w2.z; cwh.w *= w2.w;
        av = af[(3 * 2 * NF) / 4 + lane];
        float v3 = dot4(cwh, av);
#pragma unroll
        for (int off = 16; off > 0; off >>= 1) {
            v0 += __shfl_down_sync(0xffffffffu, v0, off);
            v1 += __shfl_down_sync(0xffffffffu, v1, off);
            v2 += __shfl_down_sync(0xffffffffu, v2, off);
            v3 += __shfl_down_sync(0xffffffffu, v3, off);
        }
        if (lane == 0) g_nl[n] = make_float4(v0, v1, v2, v3);
    }

    // ---- relation logits for first NR node indices ----
    if (n < NR) {
        const float4* af = (const float4*)a;
        float4 rv = r4[n * 32 + lane];
        float u0 = dot4(rv, af[(0 * 2 * NF + NF) / 4 + lane]);
        float u1 = dot4(rv, af[(1 * 2 * NF + NF) / 4 + lane]);
        float u2 = dot4(rv, af[(2 * 2 * NF + NF) / 4 + lane]);
        float u3 = dot4(rv, af[(3 * 2 * NF + NF) / 4 + lane]);
#pragma unroll
        for (int off = 16; off > 0; off >>= 1) {
            u0 += __shfl_down_sync(0xffffffffu, u0, off);
            u1 += __shfl_down_sync(0xffffffffu, u1, off);
            u2 += __shfl_down_sync(0xffffffffu, u2, off);
            u3 += __shfl_down_sync(0xffffffffu, u3, off);
        }
        if (lane == 0) g_rl[n] = make_float4(u0, u1, u2, u3);
    }

    // ---- degree histogram: this block's 96 edges (8 nodes * 12) ----
    __syncthreads();
    if (tid < 96) {
        int e = blockIdx.x * 96 + tid;
        int dst = s_is64 ? (int)((const long long*)A)[e] : ((const int*)A)[e];
        atomicAdd(&g_deg[dst], 1);
    }
}

// ---------------- 1: scan via atomic block base; self-cleans g_deg ----------------
__global__ void k_scanA() {
    __shared__ int s[256];
    __shared__ int base;
    int tid = threadIdx.x;
    int i = blockIdx.x * 256 + tid;
    int v = (i < NN) ? g_deg[i] : 0;
    s[tid] = v;
    __syncthreads();
#pragma unroll
    for (int off = 1; off < 256; off <<= 1) {
        int t = (tid >= off) ? s[tid - off] : 0;
        __syncthreads();
        s[tid] += t;
        __syncthreads();
    }
    if (tid == 255) base = atomicAdd(&g_total, s[255]);
    __syncthreads();
    if (i < NN) {
        int r = base + s[tid] - v;
        g_rowptr[i] = r;
        g_end[i]    = r + v;
        g_cursor[i] = r;
        g_deg[i]    = 0;      // clean for next launch
    }
}

// ---------------- 2: scatter edges into CSR buckets (2 edges/thread) ----------------
__global__ void k_scatter(const void* __restrict__ A) {
    int is64 = detect64((const int*)A);
    int p = blockIdx.x * blockDim.x + threadIdx.x;
    if (p >= NE / 2) return;
    int d0, d1, r0, r1, s0, s1;
    if (is64) {
        const longlong2* a = (const longlong2*)A;
        longlong2 vd = a[p];
        longlong2 vr = a[NE / 2 + p];
        longlong2 vs = a[NE + p];
        d0 = (int)vd.x; d1 = (int)vd.y;
        r0 = (int)vr.x; r1 = (int)vr.y;
        s0 = (int)vs.x; s1 = (int)vs.y;
    } else {
        const int2* a = (const int2*)A;
        int2 vd = a[p];
        int2 vr = a[NE / 2 + p];
        int2 vs = a[NE + p];
        d0 = vd.x; d1 = vd.y;
        r0 = vr.x; r1 = vr.y;
        s0 = vs.x; s1 = vs.y;
    }
    int p0 = atomicAdd(&g_cursor[d0], 1);
    g_edges[p0] = make_int2(s0, r0);
    int p1 = atomicAdd(&g_cursor[d1], 1);
    g_edges[p1] = make_int2(s1, r1);
}

// ---------------- 3: aggregation, one warp per dst node ----------------
__global__ void __launch_bounds__(32, 32) k_agg(const float4* __restrict__ h4,
                                                const float4* __restrict__ r4,
                                                const float* __restrict__ w,
                                                float* __restrict__ out) {
    int n = blockIdx.x;
    int t = threadIdx.x;
    if (n == 0 && t == 0) g_total = 0;    // clean for next launch
    int beg = g_rowptr[n];
    int end = g_end[n];

    ull aH0 = 0, aH1 = 0, aH2 = 0, aH3 = 0, aH4 = 0, aH5 = 0, aH6 = 0, aH7 = 0;
    ull aR0 = 0, aR1 = 0, aR2 = 0, aR3 = 0, aR4 = 0, aR5 = 0, aR6 = 0, aR7 = 0;
    float prs0 = 0.f, prs1 = 0.f, prs2 = 0.f, prs3 = 0.f;

    __shared__ float4 s_e[32];
    __shared__ int2 s_sr[32];

    for (int base = beg; base < end; base += 32) {
        int c = end - base;
        if (c > 32) c = 32;
        if (t < c) {
            int2 er = g_edges[base + t];
            float4 nl = g_nl[er.x];
            float4 rl = g_rl[er.y];
            float4 ev;
            ev.x = edge_e(nl.x + rl.x);
            ev.y = edge_e(nl.y + rl.y);
            ev.z = edge_e(nl.z + rl.z);
            ev.w = edge_e(nl.w + rl.w);
            s_e[t]  = ev;
            s_sr[t] = er;
            prs0 += ev.x; prs1 += ev.y; prs2 += ev.z; prs3 += ev.w;
        }
        __syncwarp();
#pragma unroll 4
        for (int j = 0; j < c; j++) {
            int2 sr = s_sr[j];
            float4 hv = h4[sr.x * 32 + t];
            float4 rv = r4[sr.y * 32 + t];
            float4 ev = s_e[j];
            ull hA = pk2(hv.x, hv.y), hB = pk2(hv.z, hv.w);
            ull rA = pk2(rv.x, rv.y), rB = pk2(rv.z, rv.w);
            ull e;
            e = pk2(ev.x, ev.x);
            aH0 = ff2(hA, e, aH0); aH1 = ff2(hB, e, aH1);
            aR0 = ff2(rA, e, aR0); aR1 = ff2(rB, e, aR1);
            e = pk2(ev.y, ev.y);
            aH2 = ff2(hA, e, aH2); aH3 = ff2(hB, e, aH3);
            aR2 = ff2(rA, e, aR2); aR3 = ff2(rB, e, aR3);
            e = pk2(ev.z, ev.z);
            aH4 = ff2(hA, e, aH4); aH5 = ff2(hB, e, aH5);
            aR4 = ff2(rA, e, aR4); aR5 = ff2(rB, e, aR5);
            e = pk2(ev.w, ev.w);
            aH6 = ff2(hA, e, aH6); aH7 = ff2(hB, e, aH7);
            aR6 = ff2(rA, e, aR6); aR7 = ff2(rB, e, aR7);
        }
        __syncwarp();
    }

#pragma unroll
    for (int off = 16; off > 0; off >>= 1) {
        prs0 += __shfl_xor_sync(0xffffffffu, prs0, off);
        prs1 += __shfl_xor_sync(0xffffffffu, prs1, off);
        prs2 += __shfl_xor_sync(0xffffffffu, prs2, off);
        prs3 += __shfl_xor_sync(0xffffffffu, prs3, off);
    }

    float4 w0 = *(const float4*)&w[0 * NF + 4 * t];
    float4 w1 = *(const float4*)&w[1 * NF + 4 * t];
    float4 w2 = *(const float4*)&w[2 * NF + 4 * t];
    float4 cw1 = w0;
    float4 cw2 = make_float4(cw1.x * w1.x, cw1.y * w1.y, cw1.z * w1.z, cw1.w * w1.w);
    float4 cw3 = make_float4(cw2.x * w2.x, cw2.y * w2.y, cw2.z * w2.z, cw2.w * w2.w);

    float i0 = 1.f / prs0, i1 = 1.f / prs1, i2 = 1.f / prs2, i3 = 1.f / prs3;
    float4* o4 = (float4*)out;
    float2 hp, rp;
    float4 o;

    hp = upk2(aH0); rp = upk2(aR0);
    o.x = (hp.x - rp.x) * i0; o.y = (hp.y - rp.y) * i0;
    hp = upk2(aH1); rp = upk2(aR1);
    o.z = (hp.x - rp.x) * i0; o.w = (hp.y - rp.y) * i0;
    o4[(0 * NN + n) * 32 + t] = o;

    hp = upk2(aH2); rp = upk2(aR2);
    o.x = (cw1.x * hp.x - rp.x) * i1; o.y = (cw1.y * hp.y - rp.y) * i1;
    hp = upk2(aH3); rp = upk2(aR3);
    o.z = (cw1.z * hp.x - rp.x) * i1; o.w = (cw1.w * hp.y - rp.y) * i1;
    o4[(1 * NN + n) * 32 + t] = o;

    hp = upk2(aH4); rp = upk2(aR4);
    o.x = (cw2.x * hp.x - rp.x) * i2; o.y = (cw2.y * hp.y - rp.y) * i2;
    hp = upk2(aH5); rp = upk2(aR5);
    o.z = (cw2.z * hp.x - rp.x) * i2; o.w = (cw2.w * hp.y - rp.y) * i2;
    o4[(2 * NN + n) * 32 + t] = o;

    hp = upk2(aH6); rp = upk2(aR6);
    o.x = (cw3.x * hp.x - rp.x) * i3; o.y = (cw3.y * hp.y - rp.y) * i3;
    hp = upk2(aH7); rp = upk2(aR7);
    o.z = (cw3.z * hp.x - rp.x) * i3; o.w = (cw3.w * hp.y - rp.y) * i3;
    o4[(3 * NN + n) * 32 + t] = o;
}

// ---------------- launch ----------------
extern "C" void kernel_launch(void* const* d_in, const int* in_sizes, int n_in,
                              void* d_out, int out_size) {
    const float* h0     = (const float*)d_in[0];
    const float* inputr = (const float*)d_in[1];
    const float* w      = (const float*)d_in[2];
    const float* a      = (const float*)d_in[3];
    const void*  A      = d_in[4];
    float* out = (float*)d_out;

    int nbN  = (NN + 255) / 256;
    int nbE2 = (NE / 2 + 255) / 256;

    k_pre<<<NN / 8, 256>>>((const float4*)h0, (const float4*)inputr, w, a, A);  // launch 0
    k_scanA<<<nbN, 256>>>();                                                     // launch 1
    k_scatter<<<nbE2, 256>>>(A);                                                 // launch 2
    k_agg<<<NN, 32>>>((const float4*)h0, (const float4*)inputr, w, out);         // launch 3
}